// round 16
// baseline (speedup 1.0000x reference)
#include <cuda_runtime.h>
#include <cstdint>

#define T_TOTAL     262144
#define NF          64
#define NP          32                  // float2 pairs per x row
#define ONP         128                 // float2 pairs per out row
#define XR4         16                  // float4 per x row
#define TILE_ROWS   256
#define HALO        90
#define SROWS       (TILE_ROWS + HALO)  // 346
#define CHUNK0_ROWS 218                 // halo + first 128 tile rows
#define CHUNK0_F4   (CHUNK0_ROWS * XR4) // 3488
#define CHUNK1_F4   ((SROWS - CHUNK0_ROWS) * XR4)  // 2048
#define SMEM_F4     (SROWS * XR4)       // 5536
#define SMEM_BYTES  (SMEM_F4 * 16)      // 88576
#define THREADS     256
#define GROUP_ROWS  32

__device__ __forceinline__ float2 f2add(float2 a, float2 b) {
    return make_float2(a.x + b.x, a.y + b.y);
}
__device__ __forceinline__ float2 f2sub(float2 a, float2 b) {
    return make_float2(a.x - b.x, a.y - b.y);
}
__device__ __forceinline__ float2 f2scale(float2 a, float s) {
    return make_float2(a.x * s, a.y * s);
}

__global__ void __launch_bounds__(THREADS, 2)
ma_kernel(const float* __restrict__ x, float* __restrict__ out) {
    extern __shared__ float4 sm4[];
    float2* sm2 = (float2*)sm4;                 // [SROWS][NP]

    const int t    = threadIdx.x;
    const int blk  = blockIdx.x;
    const int base = blk * TILE_ROWS - HALO;    // global row of smem row 0
    const int lt   = t & 127;
    const float4* x4 = (const float4*)x;

    // ---- Phase 1: split-ownership cp.async fill ----
    if (t < 128) {
        // Warps 0-3 own chunk0 = smem rows [0, 218): halo + tile rows 0..127.
        const int pad = (blk == 0) ? HALO : 0;  // rows < 0 are implicit zeros
        if (pad) {
            for (int idx = lt; idx < pad * XR4; idx += 128)
                sm4[idx] = make_float4(0.f, 0.f, 0.f, 0.f);
        }
        uint32_t sdst = (uint32_t)__cvta_generic_to_shared(sm4 + pad * XR4);
        const float4* src = x4 + (base + pad) * XR4;
        const int n4 = CHUNK0_F4 - pad * XR4;
        #pragma unroll 4
        for (int idx = lt; idx < n4; idx += 128) {
            asm volatile("cp.async.cg.shared.global [%0], [%1], 16;" ::
                         "r"(sdst + (uint32_t)idx * 16u), "l"(src + idx));
        }
        asm volatile("cp.async.commit_group;");
        asm volatile("cp.async.wait_group 0;");
        // chunk0 fully visible among warps 0-3:
        asm volatile("bar.sync 1, 128;" ::: "memory");
        // signal chunk0-ready to warps 4-7 (non-blocking):
        asm volatile("bar.arrive 2, 256;" ::: "memory");
    } else {
        // Warps 4-7 own chunk1 = smem rows [218, 346) = tile rows 128..255.
        uint32_t sdst = (uint32_t)__cvta_generic_to_shared(sm4 + CHUNK0_F4);
        const float4* src = x4 + (base + CHUNK0_ROWS) * XR4;   // >= 0 always
        #pragma unroll 4
        for (int idx = lt; idx < CHUNK1_F4; idx += 128) {
            asm volatile("cp.async.cg.shared.global [%0], [%1], 16;" ::
                         "r"(sdst + (uint32_t)idx * 16u), "l"(src + idx));
        }
        asm volatile("cp.async.commit_group;");
        asm volatile("cp.async.wait_group 0;");
        // own copies done + chunk0-ready arrivals from warps 0-3:
        asm volatile("bar.sync 2, 256;" ::: "memory");
    }

    // ---- Phase 2: one column-pair per thread, 32-row strip per group ----
    // Strips 0-3 read only smem rows [0,218) = chunk0; strips 4-7 read
    // rows [128-90+128 .. 346) which spans chunk0+chunk1 — both visible.
    const int p   = t & (NP - 1);               // column pair 0..31
    const int g   = t >> 5;                     // group 0..7
    const int lr0 = HALO + g * GROUP_ROWS;      // first smem row of strip
    const int gr0 = blk * TILE_ROWS + g * GROUP_ROWS;

    float2 s7  = make_float2(0.f, 0.f);
    float2 s30 = s7, s90 = s7;

    // Entry sums over the 90 rows preceding the strip (zero-padded for blk 0).
    #pragma unroll 10
    for (int k = 1; k <= HALO; k++) {
        float2 v = sm2[(lr0 - k) * NP + p];
        s90 = f2add(s90, v);
        if (k <= 30) s30 = f2add(s30, v);
        if (k <= 7)  s7  = f2add(s7, v);
    }

    const float inv7  = 1.0f / 7.0f;
    const float inv30 = 1.0f / 30.0f;
    const float inv90 = 1.0f / 90.0f;

    float2* oc = (float2*)out + p;              // row stride ONP

    if (gr0 < 90) {
        // Careful region (blk 0, groups 0..2): expanding divisors; zero-padded
        // halo makes the sliding sums equal the cumsum automatically.
        #pragma unroll
        for (int j = 0; j < GROUP_ROWS; j++) {
            int lr = lr0 + j;
            int gi = gr0 + j;
            float2 v   = sm2[lr * NP + p];
            float2 v7  = sm2[(lr - 7)  * NP + p];
            float2 v30 = sm2[(lr - 30) * NP + p];
            float2 v90 = sm2[(lr - 90) * NP + p];
            s7  = f2add(s7,  f2sub(v, v7));
            s30 = f2add(s30, f2sub(v, v30));
            s90 = f2add(s90, f2sub(v, v90));
            float rn  = 1.0f / (float)(gi + 1);
            float r7  = (gi >= 6)  ? inv7  : rn;
            float r30 = (gi >= 29) ? inv30 : rn;
            float r90 = (gi >= 89) ? inv90 : rn;
            float2* o = oc + (size_t)gi * ONP;
            __stcs(o,          v);
            __stcs(o + NP,     f2scale(s7,  r7));
            __stcs(o + 2 * NP, f2scale(s30, r30));
            __stcs(o + 3 * NP, f2scale(s90, r90));
        }
    } else {
        #pragma unroll
        for (int j = 0; j < GROUP_ROWS; j++) {
            int lr = lr0 + j;
            int gi = gr0 + j;
            float2 v   = sm2[lr * NP + p];
            float2 v7  = sm2[(lr - 7)  * NP + p];
            float2 v30 = sm2[(lr - 30) * NP + p];
            float2 v90 = sm2[(lr - 90) * NP + p];
            s7  = f2add(s7,  f2sub(v, v7));
            s30 = f2add(s30, f2sub(v, v30));
            s90 = f2add(s90, f2sub(v, v90));
            float2* o = oc + (size_t)gi * ONP;
            __stcs(o,          v);
            __stcs(o + NP,     f2scale(s7,  inv7));
            __stcs(o + 2 * NP, f2scale(s30, inv30));
            __stcs(o + 3 * NP, f2scale(s90, inv90));
        }
    }
}

extern "C" void kernel_launch(void* const* d_in, const int* in_sizes, int n_in,
                              void* d_out, int out_size) {
    const float* x  = (const float*)d_in[0];
    float*      out = (float*)d_out;
    static int attr_set = 0;
    if (!attr_set) {
        cudaFuncSetAttribute(ma_kernel,
                             cudaFuncAttributeMaxDynamicSharedMemorySize,
                             SMEM_BYTES);
        attr_set = 1;
    }
    int n_blocks = T_TOTAL / TILE_ROWS;         // 1024
    ma_kernel<<<n_blocks, THREADS, SMEM_BYTES>>>(x, out);
}

// round 17
// speedup vs baseline: 1.0664x; 1.0664x over previous
#include <cuda_runtime.h>
#include <cstdint>

#define T_TOTAL    262144
#define NF         64
#define NP         32                  // float2 pairs per x row
#define ONP        128                 // float2 pairs per out row
#define XR4        16                  // float4 per x row
#define TILE_ROWS  128
#define HALO       90
#define SROWS      (TILE_ROWS + HALO)  // 218
#define SMEM_F4    (SROWS * XR4)       // 3488
#define SMEM_BYTES (SMEM_F4 * 16)      // 55808
#define THREADS    128
#define GROUPS     4
#define GROUP_ROWS (TILE_ROWS / GROUPS)  // 32

__device__ __forceinline__ float2 f2add(float2 a, float2 b) {
    return make_float2(a.x + b.x, a.y + b.y);
}
__device__ __forceinline__ float2 f2sub(float2 a, float2 b) {
    return make_float2(a.x - b.x, a.y - b.y);
}
__device__ __forceinline__ float2 f2scale(float2 a, float s) {
    return make_float2(a.x * s, a.y * s);
}

__global__ void __launch_bounds__(THREADS, 4)
ma_kernel(const float* __restrict__ x, float* __restrict__ out) {
    extern __shared__ float4 sm4[];
    float2* sm2 = (float2*)sm4;                 // [SROWS][NP]

    const int t    = threadIdx.x;
    const int blk  = blockIdx.x;
    const int base = blk * TILE_ROWS - HALO;    // global row of smem row 0

    // ---- Phase 1: cp.async stream tile + halo into smem ----
    const int pad = (blk == 0) ? HALO : 0;      // rows < 0 are implicit zeros
    if (pad) {
        for (int idx = t; idx < pad * XR4; idx += THREADS)
            sm4[idx] = make_float4(0.f, 0.f, 0.f, 0.f);
    }
    {
        uint32_t sdst = (uint32_t)__cvta_generic_to_shared(sm4 + pad * XR4);
        const float4* src = (const float4*)x + (base + pad) * XR4;
        const int n4 = (SROWS - pad) * XR4;
        #pragma unroll 7
        for (int idx = t; idx < n4; idx += THREADS) {
            asm volatile("cp.async.cg.shared.global [%0], [%1], 16;" ::
                         "r"(sdst + (uint32_t)idx * 16u), "l"(src + idx));
        }
        asm volatile("cp.async.commit_group;");
        asm volatile("cp.async.wait_group 0;");
    }
    __syncthreads();

    // ---- Phase 2: one column-pair per thread, 32-row strip per group ----
    const int p   = t & (NP - 1);               // column pair 0..31
    const int g   = t >> 5;                     // group 0..3
    const int lr0 = HALO + g * GROUP_ROWS;      // first smem row of strip
    const int gr0 = blk * TILE_ROWS + g * GROUP_ROWS;

    float2 s7  = make_float2(0.f, 0.f);
    float2 s30 = s7, s90 = s7;

    // Entry sums over the 90 rows preceding the strip (zero-padded for blk 0).
    #pragma unroll 10
    for (int k = 1; k <= HALO; k++) {
        float2 v = sm2[(lr0 - k) * NP + p];
        s90 = f2add(s90, v);
        if (k <= 30) s30 = f2add(s30, v);
        if (k <= 7)  s7  = f2add(s7, v);
    }

    const float inv7  = 1.0f / 7.0f;
    const float inv30 = 1.0f / 30.0f;
    const float inv90 = 1.0f / 90.0f;

    float2* oc = (float2*)out + p;              // row stride ONP

    if (gr0 < 90) {
        // Careful region (blk 0, groups 0..2): expanding divisors; zero-padded
        // halo makes the sliding sums equal the cumsum automatically.
        #pragma unroll
        for (int j = 0; j < GROUP_ROWS; j++) {
            int lr = lr0 + j;
            int gi = gr0 + j;
            float2 v   = sm2[lr * NP + p];
            float2 v7  = sm2[(lr - 7)  * NP + p];
            float2 v30 = sm2[(lr - 30) * NP + p];
            float2 v90 = sm2[(lr - 90) * NP + p];
            s7  = f2add(s7,  f2sub(v, v7));
            s30 = f2add(s30, f2sub(v, v30));
            s90 = f2add(s90, f2sub(v, v90));
            float rn  = 1.0f / (float)(gi + 1);
            float r7  = (gi >= 6)  ? inv7  : rn;
            float r30 = (gi >= 29) ? inv30 : rn;
            float r90 = (gi >= 89) ? inv90 : rn;
            float2* o = oc + (size_t)gi * ONP;
            __stcs(o,          v);
            __stcs(o + NP,     f2scale(s7,  r7));
            __stcs(o + 2 * NP, f2scale(s30, r30));
            __stcs(o + 3 * NP, f2scale(s90, r90));
        }
    } else {
        #pragma unroll
        for (int j = 0; j < GROUP_ROWS; j++) {
            int lr = lr0 + j;
            int gi = gr0 + j;
            float2 v   = sm2[lr * NP + p];
            float2 v7  = sm2[(lr - 7)  * NP + p];
            float2 v30 = sm2[(lr - 30) * NP + p];
            float2 v90 = sm2[(lr - 90) * NP + p];
            s7  = f2add(s7,  f2sub(v, v7));
            s30 = f2add(s30, f2sub(v, v30));
            s90 = f2add(s90, f2sub(v, v90));
            float2* o = oc + (size_t)gi * ONP;
            __stcs(o,          v);
            __stcs(o + NP,     f2scale(s7,  inv7));
            __stcs(o + 2 * NP, f2scale(s30, inv30));
            __stcs(o + 3 * NP, f2scale(s90, inv90));
        }
    }
}

extern "C" void kernel_launch(void* const* d_in, const int* in_sizes, int n_in,
                              void* d_out, int out_size) {
    const float* x  = (const float*)d_in[0];
    float*      out = (float*)d_out;
    static int attr_set = 0;
    if (!attr_set) {
        cudaFuncSetAttribute(ma_kernel,
                             cudaFuncAttributeMaxDynamicSharedMemorySize,
                             SMEM_BYTES);
        attr_set = 1;
    }
    int n_blocks = T_TOTAL / TILE_ROWS;         // 2048
    ma_kernel<<<n_blocks, THREADS, SMEM_BYTES>>>(x, out);
}